// round 2
// baseline (speedup 1.0000x reference)
#include <cuda_runtime.h>
#include <math.h>

#define BATCH 16384
#define HID 256

// Output layout (float32, concatenated in reference return order):
//   [0, 4194304)            h_next  (B,1,256)
//   [4194304, 4194313)      G_structure (9 ints as float)
//   [4194313, 41943049)     G_node  (B,9,256)
//   [41943049, 41943055)    margins (6)
#define OFF_GS 4194304ul
#define OFF_GN 4194313ul
#define OFF_MG 41943049ul
#define GN_LD  2304   // 9*256 row stride of G_node

// Scratch (device globals: no allocation allowed in kernel_launch)
__device__ float g_cand[(size_t)BATCH * 768];   // candidates k=0..2 for current stage
__device__ float g_z1 [(size_t)BATCH * HID];
__device__ float g_r  [(size_t)BATCH * HID];
__device__ float g_rh [(size_t)BATCH * HID];
__device__ float g_ht [(size_t)BATCH * HID];
__device__ float g_omz[(size_t)BATCH * HID];
__device__ float g_zht[(size_t)BATCH * HID];
__device__ float g_z2h[(size_t)BATCH * HID];
__device__ double g_ssum[24];                   // 6 stages x 4 score sums

__global__ void init_kernel() {
    int t = threadIdx.x;
    if (t < 24) g_ssum[t] = 0.0;
}

// ---------------------------------------------------------------------------
// Tiled SGEMM: C[m,n] = EPI( combine(A1@W1, A2@W2)[m,n] + bias[n] )
//   MODE 0: single  (A1@W1)
//   MODE 1: dual add (A1@W1 + A2@W2)
//   MODE 2: dual mul (A1@W1) * (A2@W2)
//   EPI  0: none, 1: sigmoid, 2: (1 - v)
// W is the "cat" layout: column j selects matrix k = j>>8, col d = j&255,
// element [h][j] at Wb + k*65536 + h*256 + d. Tiles are 64-wide so each block
// stays inside one k-slab (256 % 64 == 0).
// A matrices are dense BATCH x 256 (lda = 256).
// Tile: BM=64, BN=64, BK=16, 256 threads, 4x4 microtile.
// ---------------------------------------------------------------------------
template<int MODE, int EPI>
__global__ void __launch_bounds__(256) gemm_kernel(
    const float* __restrict__ A1, const float* __restrict__ A2,
    const float* __restrict__ W1b, const float* __restrict__ W2b,
    const float* __restrict__ bias,
    float* __restrict__ C,  int ldc,
    float* __restrict__ C2, int ldc2,
    float* __restrict__ C3, int ldc3)
{
    const int bm0 = blockIdx.y * 64;
    const int bn0 = blockIdx.x * 64;

    const float* W1 = W1b + (size_t)(bn0 >> 8) * 65536 + (bn0 & 255);
    const float* W2 = (MODE != 0) ? (W2b + (size_t)(bn0 >> 8) * 65536 + (bn0 & 255))
                                  : (const float*)nullptr;

    __shared__ float As1[16][68];
    __shared__ float Ws1[16][68];
    __shared__ float As2[16][68];
    __shared__ float Ws2[16][68];

    const int tid = threadIdx.x;
    const int tx = tid & 15;        // column group (4 cols)
    const int ty = tid >> 4;        // row group (4 rows)
    const int lm = tid >> 2;        // A-load row 0..63
    const int lk = (tid & 3) * 4;   // A-load k 0,4,8,12
    const int wk = tid >> 4;        // W-load k 0..15
    const int wn = (tid & 15) * 4;  // W-load col 0..60

    float acc[4][4], acc2[4][4];
    #pragma unroll
    for (int i = 0; i < 4; i++)
        #pragma unroll
        for (int j = 0; j < 4; j++) { acc[i][j] = 0.f; acc2[i][j] = 0.f; }

    const float* a1p = A1 + (size_t)(bm0 + lm) * HID + lk;
    const float* w1p = W1 + (size_t)wk * HID + wn;
    const float* a2p = (MODE != 0) ? (A2 + (size_t)(bm0 + lm) * HID + lk) : nullptr;
    const float* w2p = (MODE != 0) ? (W2 + (size_t)wk * HID + wn) : nullptr;

    for (int k0 = 0; k0 < HID; k0 += 16) {
        float4 a1 = *(const float4*)(a1p + k0);
        float4 w1 = *(const float4*)(w1p + (size_t)k0 * HID);
        As1[lk + 0][lm] = a1.x; As1[lk + 1][lm] = a1.y;
        As1[lk + 2][lm] = a1.z; As1[lk + 3][lm] = a1.w;
        *(float4*)&Ws1[wk][wn] = w1;
        if (MODE != 0) {
            float4 a2 = *(const float4*)(a2p + k0);
            float4 w2 = *(const float4*)(w2p + (size_t)k0 * HID);
            As2[lk + 0][lm] = a2.x; As2[lk + 1][lm] = a2.y;
            As2[lk + 2][lm] = a2.z; As2[lk + 3][lm] = a2.w;
            *(float4*)&Ws2[wk][wn] = w2;
        }
        __syncthreads();

        #pragma unroll
        for (int kk = 0; kk < 16; kk++) {
            float4 af1 = *(const float4*)&As1[kk][ty * 4];
            float4 wf1 = *(const float4*)&Ws1[kk][tx * 4];
            float a1v[4] = {af1.x, af1.y, af1.z, af1.w};
            float w1v[4] = {wf1.x, wf1.y, wf1.z, wf1.w};
            #pragma unroll
            for (int i = 0; i < 4; i++)
                #pragma unroll
                for (int j = 0; j < 4; j++)
                    acc[i][j] += a1v[i] * w1v[j];
            if (MODE != 0) {
                float4 af2 = *(const float4*)&As2[kk][ty * 4];
                float4 wf2 = *(const float4*)&Ws2[kk][tx * 4];
                float a2v[4] = {af2.x, af2.y, af2.z, af2.w};
                float w2v[4] = {wf2.x, wf2.y, wf2.z, wf2.w};
                if (MODE == 1) {
                    #pragma unroll
                    for (int i = 0; i < 4; i++)
                        #pragma unroll
                        for (int j = 0; j < 4; j++)
                            acc[i][j] += a2v[i] * w2v[j];
                } else {
                    #pragma unroll
                    for (int i = 0; i < 4; i++)
                        #pragma unroll
                        for (int j = 0; j < 4; j++)
                            acc2[i][j] += a2v[i] * w2v[j];
                }
            }
        }
        __syncthreads();
    }

    #pragma unroll
    for (int i = 0; i < 4; i++) {
        int m = bm0 + ty * 4 + i;
        #pragma unroll
        for (int j = 0; j < 4; j++) {
            int n = bn0 + tx * 4 + j;
            float v = (MODE == 2) ? acc[i][j] * acc2[i][j] : acc[i][j];
            v += bias[n];
            if (EPI == 1) v = 1.f / (1.f + expf(-v));
            if (EPI == 2) v = 1.f - v;
            C[(size_t)m * ldc + n] = v;
            if (C2) C2[(size_t)m * ldc2 + n] = v;
            if (C3) C3[(size_t)m * ldc3 + n] = v;
        }
    }
}

// ---------------------------------------------------------------------------
// Mixture: per row b, candidates c[k] (k=0..2 from g_cand; k=3 via identity:
//   mode 0: a1 + a2 + b3,  mode 1: a1*a2 + b3,  mode 2: 1 - (a1 + b3))
// scores[k] = c[k] . Ws ; softmax over k ; out = sum_k w_k c[k]
// Also accumulates sum_b scores[k] into g_ssum[stage*4+k] (double atomics,
// one per block per k).
// One warp per row, 8 rows per 256-thread block.
// ---------------------------------------------------------------------------
__global__ void __launch_bounds__(256) mixture_kernel(
    const float* __restrict__ A1, const float* __restrict__ A2,
    const float* __restrict__ Wsv, const float* __restrict__ bias3,
    float* __restrict__ out1, int ld1,
    float* __restrict__ out2, int ld2,
    float* __restrict__ out3, int ld3,
    int mode, int stage)
{
    __shared__ float sWs[256];
    __shared__ float sSc[8][4];
    int tid = threadIdx.x;
    sWs[tid] = Wsv[tid];
    __syncthreads();

    int warp = tid >> 5, lane = tid & 31;
    size_t b = (size_t)blockIdx.x * 8 + warp;
    const float* crow = g_cand + b * 768;

    float c[4][8];
    #pragma unroll
    for (int k = 0; k < 3; k++)
        #pragma unroll
        for (int j = 0; j < 8; j++)
            c[k][j] = crow[k * 256 + j * 32 + lane];

    #pragma unroll
    for (int j = 0; j < 8; j++) {
        int d = j * 32 + lane;
        float a1 = A1[b * HID + d];
        float v;
        if (mode == 0)      v = a1 + A2[b * HID + d] + bias3[d];
        else if (mode == 1) v = a1 * A2[b * HID + d] + bias3[d];
        else                v = 1.f - (a1 + bias3[d]);
        c[3][j] = v;
    }

    float sc[4];
    #pragma unroll
    for (int k = 0; k < 4; k++) {
        float p = 0.f;
        #pragma unroll
        for (int j = 0; j < 8; j++) p += c[k][j] * sWs[j * 32 + lane];
        #pragma unroll
        for (int o = 16; o > 0; o >>= 1) p += __shfl_xor_sync(0xffffffffu, p, o);
        sc[k] = p;
    }

    float mx = fmaxf(fmaxf(sc[0], sc[1]), fmaxf(sc[2], sc[3]));
    float e0 = expf(sc[0] - mx), e1 = expf(sc[1] - mx);
    float e2 = expf(sc[2] - mx), e3 = expf(sc[3] - mx);
    float inv = 1.f / (e0 + e1 + e2 + e3);

    #pragma unroll
    for (int j = 0; j < 8; j++) {
        int d = j * 32 + lane;
        float o = (e0 * c[0][j] + e1 * c[1][j] + e2 * c[2][j] + e3 * c[3][j]) * inv;
        out1[b * ld1 + d] = o;
        if (out2) out2[b * ld2 + d] = o;
        if (out3) out3[b * ld3 + d] = o;
    }

    if (lane == 0) {
        sSc[warp][0] = sc[0]; sSc[warp][1] = sc[1];
        sSc[warp][2] = sc[2]; sSc[warp][3] = sc[3];
    }
    __syncthreads();
    if (tid < 4) {
        float s = 0.f;
        #pragma unroll
        for (int w = 0; w < 8; w++) s += sSc[w][tid];
        atomicAdd(&g_ssum[stage * 4 + tid], (double)s);
    }
}

__global__ void finalize_kernel(float* __restrict__ out) {
    if (threadIdx.x == 0 && blockIdx.x == 0) {
        float* gs = out + OFF_GS;
        float* mg = out + OFF_MG;
        gs[0] = 0.f; gs[1] = 1.f; gs[2] = 0.f;
        for (int s = 0; s < 6; s++) {
            double v[4];
            for (int k = 0; k < 4; k++) v[k] = g_ssum[s * 4 + k];
            int idx = 0; double m1 = v[0];
            for (int k = 1; k < 4; k++) if (v[k] > m1) { m1 = v[k]; idx = k; }
            double m2 = -1e300;
            for (int k = 0; k < 4; k++) if (k != idx && v[k] > m2) m2 = v[k];
            gs[3 + s] = (float)idx;
            mg[s] = (float)(m1 - m2);
        }
    }
}

extern "C" void kernel_launch(void* const* d_in, const int* in_sizes, int n_in,
                              void* d_out, int out_size) {
    const float* x  = (const float*)d_in[0];   // (B,1,256)
    const float* h  = (const float*)d_in[1];   // (B,1,256)
    const float* L  = (const float*)d_in[2];   // (4,256,256)
    const float* R  = (const float*)d_in[3];   // (4,256,256)
    const float* b  = (const float*)d_in[4];   // (4,256)
    const float* Ws = (const float*)d_in[5];   // (256)
    float* out = (float*)d_out;
    float* gnode = out + OFF_GN;

    float *z1p, *rp, *rhp, *htp, *omzp, *zhtp, *z2hp, *candp;
    cudaGetSymbolAddress((void**)&z1p,  g_z1);
    cudaGetSymbolAddress((void**)&rp,   g_r);
    cudaGetSymbolAddress((void**)&rhp,  g_rh);
    cudaGetSymbolAddress((void**)&htp,  g_ht);
    cudaGetSymbolAddress((void**)&omzp, g_omz);
    cudaGetSymbolAddress((void**)&zhtp, g_zht);
    cudaGetSymbolAddress((void**)&z2hp, g_z2h);
    cudaGetSymbolAddress((void**)&candp, g_cand);

    dim3 blk(256);
    dim3 gOut(4, BATCH / 64);    // N=256
    dim3 gCand(12, BATCH / 64);  // N=768 (k=0..2)
    int mixGrid = BATCH / 8;

    init_kernel<<<1, 32>>>();

    // z1 = z2 = sigmoid(x@L0 + h@R0 + b0)  -> scratch + G_node slots 0,2
    gemm_kernel<1, 1><<<gOut, blk>>>(x, h, L, R, b,
                                     z1p, HID, gnode + 0 * HID, GN_LD, gnode + 2 * HID, GN_LD);
    // r = sigmoid(x@L1 + h@R1 + b1) -> scratch + slot 1
    gemm_kernel<1, 1><<<gOut, blk>>>(x, h, L + 65536, R + 65536, b + 256,
                                     rp, HID, gnode + 1 * HID, GN_LD, nullptr, 0);

    // rh = mixture(lin(h, r))
    gemm_kernel<1, 0><<<gCand, blk>>>(h, rp, L, R, b, candp, 768, nullptr, 0, nullptr, 0);
    mixture_kernel<<<mixGrid, blk>>>(h, rp, Ws, b + 768,
                                     rhp, HID, gnode + 3 * HID, GN_LD, nullptr, 0, 0, 0);
    // h_tilde = mixture(lin(x, rh))
    gemm_kernel<1, 0><<<gCand, blk>>>(x, rhp, L, R, b, candp, 768, nullptr, 0, nullptr, 0);
    mixture_kernel<<<mixGrid, blk>>>(x, rhp, Ws, b + 768,
                                     htp, HID, gnode + 4 * HID, GN_LD, nullptr, 0, 0, 1);
    // oneMinusZ1 = mixture(1 - (z1@R + b))
    gemm_kernel<0, 2><<<gCand, blk>>>(z1p, nullptr, R, nullptr, b, candp, 768, nullptr, 0, nullptr, 0);
    mixture_kernel<<<mixGrid, blk>>>(z1p, nullptr, Ws, b + 768,
                                     omzp, HID, gnode + 5 * HID, GN_LD, nullptr, 0, 2, 2);
    // zh_tilde = mixture((h_tilde@L) * (oneMinusZ1@R) + b)
    gemm_kernel<2, 0><<<gCand, blk>>>(htp, omzp, L, R, b, candp, 768, nullptr, 0, nullptr, 0);
    mixture_kernel<<<mixGrid, blk>>>(htp, omzp, Ws, b + 768,
                                     zhtp, HID, gnode + 6 * HID, GN_LD, nullptr, 0, 1, 3);
    // z2h = mixture((h@L) * (z2@R) + b)   (z2 == z1)
    gemm_kernel<2, 0><<<gCand, blk>>>(h, z1p, L, R, b, candp, 768, nullptr, 0, nullptr, 0);
    mixture_kernel<<<mixGrid, blk>>>(h, z1p, Ws, b + 768,
                                     z2hp, HID, gnode + 7 * HID, GN_LD, nullptr, 0, 1, 4);
    // h_next = mixture(lin(zh_tilde, z2h)) -> h_next region + slot 8
    gemm_kernel<1, 0><<<gCand, blk>>>(zhtp, z2hp, L, R, b, candp, 768, nullptr, 0, nullptr, 0);
    mixture_kernel<<<mixGrid, blk>>>(zhtp, z2hp, Ws, b + 768,
                                     out, HID, gnode + 8 * HID, GN_LD, nullptr, 0, 0, 5);

    finalize_kernel<<<1, 32>>>(out);
}

// round 6
// speedup vs baseline: 1.0564x; 1.0564x over previous
#include <cuda_runtime.h>
#include <math.h>
#include <stdint.h>

#define BATCH 16384
#define HID 256

// Output layout (float32):
//   [0, 4194304)            h_next  (B,1,256)
//   [4194304, 4194313)      G_structure (9 ints as float)
//   [4194313, 41943049)     G_node  (B,9,256)   <-- base NOT 16B-aligned (offset 9 floats)
//   [41943049, 41943055)    margins (6)
#define OFF_GS 4194304ul
#define OFF_GN 4194313ul
#define OFF_MG 41943049ul
#define GN_LD  2304

// ---------------------------------------------------------------------------
// Scratch (device globals; no runtime allocation allowed). 16B-aligned:
// these are accessed through float4.
// ---------------------------------------------------------------------------
__device__ __align__(16) float g_cand [(size_t)BATCH * 768];
__device__ __align__(16) float g_cand2[(size_t)BATCH * 768];
__device__ __align__(16) float g_z1 [(size_t)BATCH * HID];
__device__ __align__(16) float g_r  [(size_t)BATCH * HID];
__device__ __align__(16) float g_rh [(size_t)BATCH * HID];
__device__ __align__(16) float g_ht [(size_t)BATCH * HID];
__device__ __align__(16) float g_omz[(size_t)BATCH * HID];
__device__ __align__(16) float g_zht[(size_t)BATCH * HID];
__device__ __align__(16) float g_z2h[(size_t)BATCH * HID];
__device__ double g_ssum[24];

__global__ void init_kernel() {
    int t = threadIdx.x;
    if (t < 24) g_ssum[t] = 0.0;
}

// ---------------------------------------------------------------------------
// SGEMM:  C = EPI( sum_{p<NPAIR} A_p @ W_p  [+ bias] )
//   A_p: [BATCH][256] fp32 row-major.
//   W_p: [4][256][256] fp32; global col n selects slab n>>8, in-slab col n&255.
//   EPI 0: +bias    1: sigmoid(+bias)    2: 1-(v+bias)    3: raw
// Tiles: BM=128, BN=128, BK=16. 256 threads, 8x8 microtile (4+4 split both
// dims), double-buffered smem. Dual pair = K_eff 512 chain, one accumulator.
// C gets float4 stores (16B-aligned targets only); C2/C3 (G_node mirrors,
// misaligned base) get scalar stores.
// ---------------------------------------------------------------------------
#define BK 16
#define LDT 132   // padded row length of smem tiles (132*4 = 528 B, 16B-mult)

template<int NPAIR, int EPI>
__global__ void __launch_bounds__(256, 2) sgemm(
    const float* __restrict__ A1, const float* __restrict__ W1,
    const float* __restrict__ A2, const float* __restrict__ W2,
    const float* __restrict__ bias,
    float* __restrict__ C,  int ldc,
    float* __restrict__ C2, int ldc2,
    float* __restrict__ C3, int ldc3)
{
    __shared__ __align__(16) float As[2][BK][LDT];   // [k][m]
    __shared__ __align__(16) float Bs[2][BK][LDT];   // [k][n]

    const int tid = threadIdx.x;
    const int tx = tid & 15;           // n microtile group
    const int ty = tid >> 4;           // m microtile group
    const int bm0 = blockIdx.y * 128;
    const int n0g = blockIdx.x * 128;  // global col base
    const int slab = n0g >> 8;
    const int n_in = n0g & 255;

    // A-load decomposition: 2 float4 per thread per chunk
    const int ar0 = (tid * 2) >> 2;          // row of first quad
    const int as0 = (tid * 2) & 3;           // k-seg of first quad
    const int ar1 = (tid * 2 + 1) >> 2;
    const int as1 = (tid * 2 + 1) & 3;
    // B-load decomposition
    const int bk0 = (tid * 2) >> 5;          // k row
    const int bc0 = (tid * 2) & 31;          // col quad
    const int bk1 = (tid * 2 + 1) >> 5;
    const int bc1 = (tid * 2 + 1) & 31;

    float acc[8][8];
    #pragma unroll
    for (int i = 0; i < 8; i++)
        #pragma unroll
        for (int j = 0; j < 8; j++) acc[i][j] = 0.f;

    float4 pa0, pa1, pb0, pb1;
    const int T = NPAIR * 16;

    auto ldg = [&](int q) {
        const float* Ap = (NPAIR == 2 && (q >> 4)) ? A2 : A1;
        const float* Wp = (NPAIR == 2 && (q >> 4)) ? W2 : W1;
        const int kb = (q & 15) * 16;
        pa0 = *(const float4*)(Ap + (size_t)(bm0 + ar0) * 256 + kb + as0 * 4);
        pa1 = *(const float4*)(Ap + (size_t)(bm0 + ar1) * 256 + kb + as1 * 4);
        const float* wbase = Wp + (size_t)slab * 65536 + (size_t)kb * 256 + n_in;
        pb0 = *(const float4*)(wbase + (size_t)bk0 * 256 + bc0 * 4);
        pb1 = *(const float4*)(wbase + (size_t)bk1 * 256 + bc1 * 4);
    };
    auto sts = [&](int s) {
        As[s][as0 * 4 + 0][ar0] = pa0.x; As[s][as0 * 4 + 1][ar0] = pa0.y;
        As[s][as0 * 4 + 2][ar0] = pa0.z; As[s][as0 * 4 + 3][ar0] = pa0.w;
        As[s][as1 * 4 + 0][ar1] = pa1.x; As[s][as1 * 4 + 1][ar1] = pa1.y;
        As[s][as1 * 4 + 2][ar1] = pa1.z; As[s][as1 * 4 + 3][ar1] = pa1.w;
        *(float4*)&Bs[s][bk0][bc0 * 4] = pb0;
        *(float4*)&Bs[s][bk1][bc1 * 4] = pb1;
    };

    ldg(0); sts(0);
    __syncthreads();

    for (int q = 0; q < T; q++) {
        const int cur = q & 1;
        if (q + 1 < T) ldg(q + 1);
        #pragma unroll
        for (int kk = 0; kk < BK; kk++) {
            float4 a0 = *(const float4*)&As[cur][kk][ty * 4];
            float4 a1 = *(const float4*)&As[cur][kk][64 + ty * 4];
            float4 b0 = *(const float4*)&Bs[cur][kk][tx * 4];
            float4 b1 = *(const float4*)&Bs[cur][kk][64 + tx * 4];
            float av[8] = {a0.x, a0.y, a0.z, a0.w, a1.x, a1.y, a1.z, a1.w};
            float bv[8] = {b0.x, b0.y, b0.z, b0.w, b1.x, b1.y, b1.z, b1.w};
            #pragma unroll
            for (int i = 0; i < 8; i++)
                #pragma unroll
                for (int j = 0; j < 8; j++)
                    acc[i][j] = fmaf(av[i], bv[j], acc[i][j]);
        }
        if (q + 1 < T) sts((q + 1) & 1);
        __syncthreads();
    }

    // Epilogue: rows {ty*4+i, 64+ty*4+i}, cols {tx*4+j, 64+tx*4+j}
    #pragma unroll
    for (int i = 0; i < 8; i++) {
        const int r = (i < 4) ? (ty * 4 + i) : (64 + ty * 4 + (i - 4));
        const size_t m = (size_t)(bm0 + r);
        #pragma unroll
        for (int half = 0; half < 2; half++) {
            const int cb = half * 64 + tx * 4;
            float4 v;
            float* vp = &v.x;
            #pragma unroll
            for (int j = 0; j < 4; j++) {
                float t = acc[i][half * 4 + j];
                if (EPI != 3) t += bias[n0g + cb + j];
                if (EPI == 1) t = 1.f / (1.f + expf(-t));
                if (EPI == 2) t = 1.f - t;
                vp[j] = t;
            }
            // C targets are 16B-aligned (scratch globals / d_out base)
            *(float4*)(C + m * ldc + n0g + cb) = v;
            // C2/C3 point into G_node (base misaligned by 9 floats): scalar stores
            if (C2) {
                float* p2 = C2 + m * ldc2 + n0g + cb;
                p2[0] = v.x; p2[1] = v.y; p2[2] = v.z; p2[3] = v.w;
            }
            if (C3) {
                float* p3 = C3 + m * ldc3 + n0g + cb;
                p3[0] = v.x; p3[1] = v.y; p3[2] = v.z; p3[3] = v.w;
            }
        }
    }
}

// ---------------------------------------------------------------------------
// Mixture over 4 candidates; k=0..2 from g_cand (mode 1: g_cand*g_cand2+b),
// k=3 built from identity slab:  mode 0: a1+a2+b3 | mode 1: a1*a2+b3
//                                mode 2: 1-(a1+b3)
// One warp per row. Also accumulates per-stage score sums (double atomics).
// ---------------------------------------------------------------------------
__global__ void __launch_bounds__(256) mixture_kernel(
    const float* __restrict__ A1, const float* __restrict__ A2,
    const float* __restrict__ Wsv, const float* __restrict__ ball,
    float* __restrict__ out1, int ld1,
    float* __restrict__ out2, int ld2,
    int mode, int stage)
{
    __shared__ float sWs[256];
    __shared__ float sSc[8][4];
    int tid = threadIdx.x;
    sWs[tid] = Wsv[tid];
    __syncthreads();

    int warp = tid >> 5, lane = tid & 31;
    size_t b = (size_t)blockIdx.x * 8 + warp;
    const float* crow  = g_cand  + b * 768;
    const float* crow2 = g_cand2 + b * 768;
    const float* bias3 = ball + 768;

    float c[4][8];
    #pragma unroll
    for (int k = 0; k < 3; k++)
        #pragma unroll
        for (int j = 0; j < 8; j++) {
            int d = j * 32 + lane;
            float v = crow[k * 256 + d];
            if (mode == 1) v = v * crow2[k * 256 + d] + ball[k * 256 + d];
            c[k][j] = v;
        }

    #pragma unroll
    for (int j = 0; j < 8; j++) {
        int d = j * 32 + lane;
        float a1 = A1[b * HID + d];
        float v;
        if (mode == 0)      v = a1 + A2[b * HID + d] + bias3[d];
        else if (mode == 1) v = a1 * A2[b * HID + d] + bias3[d];
        else                v = 1.f - (a1 + bias3[d]);
        c[3][j] = v;
    }

    float sc[4];
    #pragma unroll
    for (int k = 0; k < 4; k++) {
        float p = 0.f;
        #pragma unroll
        for (int j = 0; j < 8; j++) p += c[k][j] * sWs[j * 32 + lane];
        #pragma unroll
        for (int o = 16; o > 0; o >>= 1) p += __shfl_xor_sync(0xffffffffu, p, o);
        sc[k] = p;
    }

    float mx = fmaxf(fmaxf(sc[0], sc[1]), fmaxf(sc[2], sc[3]));
    float e0 = expf(sc[0] - mx), e1 = expf(sc[1] - mx);
    float e2 = expf(sc[2] - mx), e3 = expf(sc[3] - mx);
    float inv = 1.f / (e0 + e1 + e2 + e3);

    #pragma unroll
    for (int j = 0; j < 8; j++) {
        int d = j * 32 + lane;
        float o = (e0 * c[0][j] + e1 * c[1][j] + e2 * c[2][j] + e3 * c[3][j]) * inv;
        out1[b * ld1 + d] = o;
        if (out2) out2[b * ld2 + d] = o;
    }

    if (lane == 0) {
        sSc[warp][0] = sc[0]; sSc[warp][1] = sc[1];
        sSc[warp][2] = sc[2]; sSc[warp][3] = sc[3];
    }
    __syncthreads();
    if (tid < 4) {
        float s = 0.f;
        #pragma unroll
        for (int w = 0; w < 8; w++) s += sSc[w][tid];
        atomicAdd(&g_ssum[stage * 4 + tid], (double)s);
    }
}

__global__ void finalize_kernel(float* __restrict__ out) {
    if (threadIdx.x == 0 && blockIdx.x == 0) {
        float* gs = out + OFF_GS;
        float* mg = out + OFF_MG;
        gs[0] = 0.f; gs[1] = 1.f; gs[2] = 0.f;
        for (int s = 0; s < 6; s++) {
            double v[4];
            for (int k = 0; k < 4; k++) v[k] = g_ssum[s * 4 + k];
            int idx = 0; double m1 = v[0];
            for (int k = 1; k < 4; k++) if (v[k] > m1) { m1 = v[k]; idx = k; }
            double m2 = -1e300;
            for (int k = 0; k < 4; k++) if (k != idx && v[k] > m2) m2 = v[k];
            gs[3 + s] = (float)idx;
            mg[s] = (float)(m1 - m2);
        }
    }
}

// ---------------------------------------------------------------------------
extern "C" void kernel_launch(void* const* d_in, const int* in_sizes, int n_in,
                              void* d_out, int out_size) {
    const float* x  = (const float*)d_in[0];
    const float* h  = (const float*)d_in[1];
    const float* L  = (const float*)d_in[2];
    const float* R  = (const float*)d_in[3];
    const float* b  = (const float*)d_in[4];
    const float* Ws = (const float*)d_in[5];
    float* out = (float*)d_out;
    float* gnode = out + OFF_GN;

    float *z1p, *rp, *rhp, *htp, *omzp, *zhtp, *z2hp, *candp, *cand2p;
    cudaGetSymbolAddress((void**)&z1p,  g_z1);
    cudaGetSymbolAddress((void**)&rp,   g_r);
    cudaGetSymbolAddress((void**)&rhp,  g_rh);
    cudaGetSymbolAddress((void**)&htp,  g_ht);
    cudaGetSymbolAddress((void**)&omzp, g_omz);
    cudaGetSymbolAddress((void**)&zhtp, g_zht);
    cudaGetSymbolAddress((void**)&z2hp, g_z2h);
    cudaGetSymbolAddress((void**)&candp, g_cand);
    cudaGetSymbolAddress((void**)&cand2p, g_cand2);

    dim3 blk(256);
    dim3 gSig(2, BATCH / 128);    // N=256
    dim3 gCand(6, BATCH / 128);   // N=768
    int mixGrid = BATCH / 8;

    init_kernel<<<1, 32>>>();

    // z1 = z2 = sigmoid(x@L0 + h@R0 + b0) -> scratch + G_node slots 0,2
    sgemm<2, 1><<<gSig, blk>>>(x, L, h, R, b,
        z1p, HID, gnode + 0 * HID, GN_LD, gnode + 2 * HID, GN_LD);
    // r = sigmoid(x@L1 + h@R1 + b1) -> scratch + slot 1
    sgemm<2, 1><<<gSig, blk>>>(x, L + 65536, h, R + 65536, b + 256,
        rp, HID, gnode + 1 * HID, GN_LD, nullptr, 0);

    // rh = mixture(h@L + r@R + b)
    sgemm<2, 0><<<gCand, blk>>>(h, L, rp, R, b, candp, 768, nullptr, 0, nullptr, 0);
    mixture_kernel<<<mixGrid, 256>>>(h, rp, Ws, b,
        rhp, HID, gnode + 3 * HID, GN_LD, 0, 0);
    // h_tilde = mixture(x@L + rh@R + b)
    sgemm<2, 0><<<gCand, blk>>>(x, L, rhp, R, b, candp, 768, nullptr, 0, nullptr, 0);
    mixture_kernel<<<mixGrid, 256>>>(x, rhp, Ws, b,
        htp, HID, gnode + 4 * HID, GN_LD, 0, 1);
    // oneMinusZ1 = mixture(1 - (z1@R + b))
    sgemm<1, 2><<<gCand, blk>>>(z1p, R, nullptr, nullptr, b, candp, 768, nullptr, 0, nullptr, 0);
    mixture_kernel<<<mixGrid, 256>>>(z1p, nullptr, Ws, b,
        omzp, HID, gnode + 5 * HID, GN_LD, 2, 2);
    // zh_tilde = mixture((ht@L) * (omz@R) + b)  -- raw products, combined in mixture
    sgemm<1, 3><<<gCand, blk>>>(htp,  L, nullptr, nullptr, b, candp,  768, nullptr, 0, nullptr, 0);
    sgemm<1, 3><<<gCand, blk>>>(omzp, R, nullptr, nullptr, b, cand2p, 768, nullptr, 0, nullptr, 0);
    mixture_kernel<<<mixGrid, 256>>>(htp, omzp, Ws, b,
        zhtp, HID, gnode + 6 * HID, GN_LD, 1, 3);
    // z2h = mixture((h@L) * (z1@R) + b)
    sgemm<1, 3><<<gCand, blk>>>(h,   L, nullptr, nullptr, b, candp,  768, nullptr, 0, nullptr, 0);
    sgemm<1, 3><<<gCand, blk>>>(z1p, R, nullptr, nullptr, b, cand2p, 768, nullptr, 0, nullptr, 0);
    mixture_kernel<<<mixGrid, 256>>>(h, z1p, Ws, b,
        z2hp, HID, gnode + 7 * HID, GN_LD, 1, 4);
    // h_next = mixture(zht@L + z2h@R + b) -> h_next region + slot 8
    sgemm<2, 0><<<gCand, blk>>>(zhtp, L, z2hp, R, b, candp, 768, nullptr, 0, nullptr, 0);
    mixture_kernel<<<mixGrid, 256>>>(zhtp, z2hp, Ws, b,
        out, HID, gnode + 8 * HID, GN_LD, 0, 5);

    finalize_kernel<<<1, 32>>>(out);
}

// round 7
// speedup vs baseline: 1.6069x; 1.5211x over previous
#include <cuda_runtime.h>
#include <cuda_bf16.h>
#include <math.h>
#include <stdint.h>

#define BATCH 16384
#define HID 256

// Output layout (float32):
//   [0, 4194304)            h_next  (B,1,256)
//   [4194304, 4194313)      G_structure (9 floats)
//   [4194313, 41943049)     G_node  (B,9,256)   <-- base NOT 16B-aligned (offset 9 floats)
//   [41943049, 41943055)    margins (6)
#define OFF_GS 4194304ul
#define OFF_GN 4194313ul
#define OFF_MG 41943049ul
#define GN_LD  2304

// ---------------------------------------------------------------------------
// Scratch (device globals). 16B-aligned (vector access).
// ---------------------------------------------------------------------------
__device__ __align__(16) float g_cand [(size_t)BATCH * 768];
__device__ __align__(16) float g_cand2[(size_t)BATCH * 768];
__device__ __align__(16) float g_z1 [(size_t)BATCH * HID];
__device__ __align__(16) float g_r  [(size_t)BATCH * HID];
__device__ __align__(16) float g_rh [(size_t)BATCH * HID];
__device__ __align__(16) float g_ht [(size_t)BATCH * HID];
__device__ __align__(16) float g_omz[(size_t)BATCH * HID];
__device__ __align__(16) float g_zht[(size_t)BATCH * HID];
__device__ __align__(16) float g_z2h[(size_t)BATCH * HID];
__device__ double g_ssum[24];

// split-bf16 activations (hi/lo)
#define ACT_ELEMS ((size_t)BATCH * HID)
__device__ __align__(16) __nv_bfloat16 g_xhi[ACT_ELEMS],  g_xlo[ACT_ELEMS];
__device__ __align__(16) __nv_bfloat16 g_hhi[ACT_ELEMS],  g_hlo[ACT_ELEMS];
__device__ __align__(16) __nv_bfloat16 g_z1hi[ACT_ELEMS], g_z1lo[ACT_ELEMS];
__device__ __align__(16) __nv_bfloat16 g_rhi[ACT_ELEMS],  g_rlo[ACT_ELEMS];
__device__ __align__(16) __nv_bfloat16 g_rhhi[ACT_ELEMS], g_rhlo[ACT_ELEMS];
__device__ __align__(16) __nv_bfloat16 g_hthi[ACT_ELEMS], g_htlo[ACT_ELEMS];
__device__ __align__(16) __nv_bfloat16 g_omzhi[ACT_ELEMS],g_omzlo[ACT_ELEMS];
__device__ __align__(16) __nv_bfloat16 g_zhthi[ACT_ELEMS],g_zhtlo[ACT_ELEMS];
__device__ __align__(16) __nv_bfloat16 g_z2hhi[ACT_ELEMS],g_z2hlo[ACT_ELEMS];

// split-bf16 weights, transposed [slab][n][k], slabs 0..2
#define W_ELEMS (3 * 65536)
__device__ __align__(16) __nv_bfloat16 g_WLhi[W_ELEMS], g_WLlo[W_ELEMS];
__device__ __align__(16) __nv_bfloat16 g_WRhi[W_ELEMS], g_WRlo[W_ELEMS];

__global__ void init_kernel() {
    int t = threadIdx.x;
    if (t < 24) g_ssum[t] = 0.0;
}

// W[s][k][n] fp32 -> hi/lo[s][n][k] bf16 (slabs 0..2)
__global__ void prep_w(const float* __restrict__ W,
                       __nv_bfloat16* __restrict__ hi, __nv_bfloat16* __restrict__ lo) {
    int i = blockIdx.x * 256 + threadIdx.x;          // s*65536 + k*256 + n
    int s = i >> 16, rem = i & 65535, k = rem >> 8, n = rem & 255;
    float v = W[i];
    __nv_bfloat16 h = __float2bfloat16(v);
    size_t o = (size_t)s * 65536 + (size_t)n * 256 + k;
    hi[o] = h;
    lo[o] = __float2bfloat16(v - __bfloat162float(h));
}

__global__ void prep_a(const float* __restrict__ A,
                       __nv_bfloat16* __restrict__ hi, __nv_bfloat16* __restrict__ lo) {
    size_t i = (size_t)blockIdx.x * 256 + threadIdx.x;
    float v = A[i];
    __nv_bfloat16 h = __float2bfloat16(v);
    hi[i] = h;
    lo[i] = __float2bfloat16(v - __bfloat162float(h));
}

// ---------------------------------------------------------------------------
// Tensor-core GEMM via warp mma.sync (bf16, fp32 accum), 3-term split:
//   A@W = Ahi@Whi + Alo@Whi + Ahi@Wlo   (virtual K = 3*256 per pair)
// NPAIR 2 folds the second pair into the same accumulator (K_eff 1536).
// EPI 0:+bias  1:sigmoid(+bias)  2:1-(v+bias)  3:raw
// CTA 128x128, 8 warps (2x4), warp tile 64x32, cp.async double buffer.
// ---------------------------------------------------------------------------
#define SROW 144                      // padded smem row bytes (64 bf16 + 8 pad)
#define SAB  18432                    // one tile (128 * 144)
// smem: A0 | B0 | A1 | B1
#define SMEM_TOT (4 * SAB)

__device__ __forceinline__ uint32_t smem_u32(const void* p) {
    uint32_t a;
    asm("{ .reg .u64 t; cvta.to.shared.u64 t, %1; cvt.u32.u64 %0, t; }" : "=r"(a) : "l"(p));
    return a;
}
#define CP_ASYNC16(dst, src) \
    asm volatile("cp.async.cg.shared.global [%0], [%1], 16;" :: "r"(dst), "l"(src))
#define CP_COMMIT() asm volatile("cp.async.commit_group;")
#define LDSM_X4(r, addr) \
    asm volatile("ldmatrix.sync.aligned.m8n8.x4.shared.b16 {%0,%1,%2,%3}, [%4];" \
        : "=r"((r)[0]), "=r"((r)[1]), "=r"((r)[2]), "=r"((r)[3]) : "r"(addr))
#define MMA16816(c, a, b0, b1) \
    asm volatile("mma.sync.aligned.m16n8k16.row.col.f32.bf16.bf16.f32 " \
        "{%0,%1,%2,%3}, {%4,%5,%6,%7}, {%8,%9}, {%0,%1,%2,%3};" \
        : "+f"((c)[0]), "+f"((c)[1]), "+f"((c)[2]), "+f"((c)[3]) \
        : "r"((a)[0]), "r"((a)[1]), "r"((a)[2]), "r"((a)[3]), "r"(b0), "r"(b1))

template<int NPAIR, int EPI>
__global__ void __launch_bounds__(256) mma_gemm(
    const __nv_bfloat16* __restrict__ A1hi, const __nv_bfloat16* __restrict__ A1lo,
    const __nv_bfloat16* __restrict__ B1hi, const __nv_bfloat16* __restrict__ B1lo,
    const __nv_bfloat16* __restrict__ A2hi, const __nv_bfloat16* __restrict__ A2lo,
    const __nv_bfloat16* __restrict__ B2hi, const __nv_bfloat16* __restrict__ B2lo,
    const float* __restrict__ bias,
    float* __restrict__ C,  int ldc,
    float* __restrict__ C2, int ldc2,
    float* __restrict__ C3, int ldc3,
    __nv_bfloat16* __restrict__ Ohi, __nv_bfloat16* __restrict__ Olo)
{
    extern __shared__ __align__(16) char smem[];
    const int tid = threadIdx.x, wid = tid >> 5, lane = tid & 31;
    const int wm = wid >> 2, wn = wid & 3;
    const int bm0 = blockIdx.y * 128;
    const int nglob = blockIdx.x * 128;
    const int slab = nglob >> 8, nr = nglob & 255;
    const uint32_t sb = smem_u32(smem);
    constexpr int NCH = NPAIR * 12;

    // loader indices: thread -> (row, 64B-half)
    const int lr = tid >> 1, lh = tid & 1;
    const size_t gArow = (size_t)(bm0 + lr) * 256 + lh * 32;
    const size_t gBrow = (size_t)slab * 65536 + (size_t)(nr + lr) * 256 + lh * 32;
    const uint32_t sOff = lr * SROW + lh * 64;

    auto issue = [&](int c) {
        const int p  = (NPAIR == 2) ? (c / 12) : 0;
        const int cc = (NPAIR == 2) ? (c % 12) : c;
        const int seg = cc >> 2;
        const int k0 = (cc & 3) * 64;
        const __nv_bfloat16* gA = (seg == 1) ? (p ? A2lo : A1lo) : (p ? A2hi : A1hi);
        const __nv_bfloat16* gB = (seg == 2) ? (p ? B2lo : B1lo) : (p ? B2hi : B1hi);
        const char* srcA = (const char*)(gA + gArow + k0);
        const char* srcB = (const char*)(gB + gBrow + k0);
        const int buf = c & 1;
        uint32_t dA = sb + buf * 2 * SAB + sOff;          // A buf
        uint32_t dB = sb + buf * 2 * SAB + SAB + sOff;    // B buf
        #pragma unroll
        for (int i = 0; i < 4; i++) CP_ASYNC16(dA + i * 16, srcA + i * 16);
        #pragma unroll
        for (int i = 0; i < 4; i++) CP_ASYNC16(dB + i * 16, srcB + i * 16);
    };

    float acc[4][4][4];
    #pragma unroll
    for (int i = 0; i < 4; i++)
        #pragma unroll
        for (int j = 0; j < 4; j++)
            #pragma unroll
            for (int t = 0; t < 4; t++) acc[i][j][t] = 0.f;

    // per-lane fragment address offsets
    const uint32_t aLane = (lane & 15) * SROW + (lane >> 4) * 16;
    const uint32_t bLane = ((lane & 7) + ((lane >= 16) ? 8 : 0)) * SROW + ((lane >> 3) & 1) * 16;

    issue(0); CP_COMMIT();

    for (int c = 0; c < NCH; c++) {
        if (c + 1 < NCH) {
            issue(c + 1); CP_COMMIT();
            asm volatile("cp.async.wait_group 1;");
        } else {
            asm volatile("cp.async.wait_group 0;");
        }
        __syncthreads();

        const int buf = c & 1;
        const uint32_t aBase = sb + buf * 2 * SAB + (wm * 64) * SROW + aLane;
        const uint32_t bBase = sb + buf * 2 * SAB + SAB + (wn * 32) * SROW + bLane;
        #pragma unroll
        for (int ks = 0; ks < 4; ks++) {
            uint32_t a[4][4];
            #pragma unroll
            for (int mt = 0; mt < 4; mt++)
                LDSM_X4(a[mt], aBase + mt * 16 * SROW + ks * 32);
            uint32_t bf[2][4];
            #pragma unroll
            for (int np = 0; np < 2; np++)
                LDSM_X4(bf[np], bBase + np * 16 * SROW + ks * 32);
            #pragma unroll
            for (int mt = 0; mt < 4; mt++)
                #pragma unroll
                for (int nt = 0; nt < 4; nt++)
                    MMA16816(acc[mt][nt], a[mt],
                             bf[nt >> 1][(nt & 1) * 2], bf[nt >> 1][(nt & 1) * 2 + 1]);
        }
        __syncthreads();
    }

    // Epilogue
    const int lr4 = lane >> 2, lc2 = (lane & 3) * 2;
    #pragma unroll
    for (int mt = 0; mt < 4; mt++) {
        #pragma unroll
        for (int nt = 0; nt < 4; nt++) {
            const int row0 = bm0 + wm * 64 + mt * 16 + lr4;
            const int gcol = nglob + wn * 32 + nt * 8 + lc2;
            const float b0v = (EPI != 3) ? bias[gcol] : 0.f;
            const float b1v = (EPI != 3) ? bias[gcol + 1] : 0.f;
            #pragma unroll
            for (int half = 0; half < 2; half++) {
                const int row = row0 + half * 8;
                float t0 = acc[mt][nt][half * 2 + 0] + b0v;
                float t1 = acc[mt][nt][half * 2 + 1] + b1v;
                if (EPI == 1) { t0 = 1.f / (1.f + expf(-t0)); t1 = 1.f / (1.f + expf(-t1)); }
                if (EPI == 2) { t0 = 1.f - t0; t1 = 1.f - t1; }
                float2 v = make_float2(t0, t1);
                *(float2*)(C + (size_t)row * ldc + gcol) = v;
                if (C2) {                       // G_node mirror: misaligned base -> scalars
                    float* p2 = C2 + (size_t)row * ldc2 + gcol;
                    p2[0] = t0; p2[1] = t1;
                }
                if (C3) {
                    float* p3 = C3 + (size_t)row * ldc3 + gcol;
                    p3[0] = t0; p3[1] = t1;
                }
                if (Ohi) {
                    __nv_bfloat16 h0 = __float2bfloat16(t0);
                    __nv_bfloat16 h1 = __float2bfloat16(t1);
                    __nv_bfloat162 hv; hv.x = h0; hv.y = h1;
                    __nv_bfloat162 lv;
                    lv.x = __float2bfloat16(t0 - __bfloat162float(h0));
                    lv.y = __float2bfloat16(t1 - __bfloat162float(h1));
                    *(__nv_bfloat162*)(Ohi + (size_t)row * HID + gcol) = hv;
                    *(__nv_bfloat162*)(Olo + (size_t)row * HID + gcol) = lv;
                }
            }
        }
    }
}

// ---------------------------------------------------------------------------
// Mixture (one warp per row). mode 0: k3 = a1+a2+b3 | mode 1: cands are raw
// products (cand*cand2+b), k3 = a1*a2+b3 | mode 2: k3 = 1-(a1+b3).
// Emits fp32 outputs (+G_node mirror) and optional bf16 hi/lo for chaining.
// ---------------------------------------------------------------------------
__global__ void __launch_bounds__(256) mixture_kernel(
    const float* __restrict__ A1, const float* __restrict__ A2,
    const float* __restrict__ Wsv, const float* __restrict__ ball,
    float* __restrict__ out1, int ld1,
    float* __restrict__ out2, int ld2,
    __nv_bfloat16* __restrict__ Ohi, __nv_bfloat16* __restrict__ Olo,
    int mode, int stage)
{
    __shared__ float sWs[256];
    __shared__ float sSc[8][4];
    int tid = threadIdx.x;
    sWs[tid] = Wsv[tid];
    __syncthreads();

    int warp = tid >> 5, lane = tid & 31;
    size_t b = (size_t)blockIdx.x * 8 + warp;
    const float* crow  = g_cand  + b * 768;
    const float* crow2 = g_cand2 + b * 768;
    const float* bias3 = ball + 768;

    float c[4][8];
    #pragma unroll
    for (int k = 0; k < 3; k++)
        #pragma unroll
        for (int j = 0; j < 8; j++) {
            int d = j * 32 + lane;
            float v = crow[k * 256 + d];
            if (mode == 1) v = v * crow2[k * 256 + d] + ball[k * 256 + d];
            c[k][j] = v;
        }

    #pragma unroll
    for (int j = 0; j < 8; j++) {
        int d = j * 32 + lane;
        float a1 = A1[b * HID + d];
        float v;
        if (mode == 0)      v = a1 + A2[b * HID + d] + bias3[d];
        else if (mode == 1) v = a1 * A2[b * HID + d] + bias3[d];
        else                v = 1.f - (a1 + bias3[d]);
        c[3][j] = v;
    }

    float sc[4];
    #pragma unroll
    for (int k = 0; k < 4; k++) {
        float p = 0.f;
        #pragma unroll
        for (int j = 0; j < 8; j++) p += c[k][j] * sWs[j * 32 + lane];
        #pragma unroll
        for (int o = 16; o > 0; o >>= 1) p += __shfl_xor_sync(0xffffffffu, p, o);
        sc[k] = p;
    }

    float mx = fmaxf(fmaxf(sc[0], sc[1]), fmaxf(sc[2], sc[3]));
    float e0 = expf(sc[0] - mx), e1 = expf(sc[1] - mx);
    float e2 = expf(sc[2] - mx), e3 = expf(sc[3] - mx);
    float inv = 1.f / (e0 + e1 + e2 + e3);

    #pragma unroll
    for (int j = 0; j < 8; j++) {
        int d = j * 32 + lane;
        float o = (e0 * c[0][j] + e1 * c[1][j] + e2 * c[2][j] + e3 * c[3][j]) * inv;
        out1[b * ld1 + d] = o;
        if (out2) out2[b * ld2 + d] = o;
        if (Ohi) {
            __nv_bfloat16 hv = __float2bfloat16(o);
            Ohi[b * HID + d] = hv;
            Olo[b * HID + d] = __float2bfloat16(o - __bfloat162float(hv));
        }
    }

    if (lane == 0) {
        sSc[warp][0] = sc[0]; sSc[warp][1] = sc[1];
        sSc[warp][2] = sc[2]; sSc[warp][3] = sc[3];
    }
    __syncthreads();
    if (tid < 4) {
        float s = 0.f;
        #pragma unroll
        for (int w = 0; w < 8; w++) s += sSc[w][tid];
        atomicAdd(&g_ssum[stage * 4 + tid], (double)s);
    }
}

__global__ void finalize_kernel(float* __restrict__ out) {
    if (threadIdx.x == 0 && blockIdx.x == 0) {
        float* gs = out + OFF_GS;
        float* mg = out + OFF_MG;
        gs[0] = 0.f; gs[1] = 1.f; gs[2] = 0.f;
        for (int s = 0; s < 6; s++) {
            double v[4];
            for (int k = 0; k < 4; k++) v[k] = g_ssum[s * 4 + k];
            int idx = 0; double m1 = v[0];
            for (int k = 1; k < 4; k++) if (v[k] > m1) { m1 = v[k]; idx = k; }
            double m2 = -1e300;
            for (int k = 0; k < 4; k++) if (k != idx && v[k] > m2) m2 = v[k];
            gs[3 + s] = (float)idx;
            mg[s] = (float)(m1 - m2);
        }
    }
}

// ---------------------------------------------------------------------------
extern "C" void kernel_launch(void* const* d_in, const int* in_sizes, int n_in,
                              void* d_out, int out_size) {
    const float* x  = (const float*)d_in[0];
    const float* h  = (const float*)d_in[1];
    const float* L  = (const float*)d_in[2];
    const float* R  = (const float*)d_in[3];
    const float* b  = (const float*)d_in[4];
    const float* Ws = (const float*)d_in[5];
    float* out = (float*)d_out;
    float* gnode = out + OFF_GN;

    float *z1p, *rp, *rhp, *htp, *omzp, *zhtp, *z2hp, *candp, *cand2p;
    cudaGetSymbolAddress((void**)&z1p,  g_z1);
    cudaGetSymbolAddress((void**)&rp,   g_r);
    cudaGetSymbolAddress((void**)&rhp,  g_rh);
    cudaGetSymbolAddress((void**)&htp,  g_ht);
    cudaGetSymbolAddress((void**)&omzp, g_omz);
    cudaGetSymbolAddress((void**)&zhtp, g_zht);
    cudaGetSymbolAddress((void**)&z2hp, g_z2h);
    cudaGetSymbolAddress((void**)&candp, g_cand);
    cudaGetSymbolAddress((void**)&cand2p, g_cand2);

    __nv_bfloat16 *xhi,*xlo,*hhi,*hlo,*z1hi,*z1lo,*rhi,*rlo,*rhhi,*rhlo,
                  *hthi,*htlo,*omzhi,*omzlo,*zhthi,*zhtlo,*z2hhi,*z2hlo,
                  *WLhi,*WLlo,*WRhi,*WRlo;
    cudaGetSymbolAddress((void**)&xhi, g_xhi);   cudaGetSymbolAddress((void**)&xlo, g_xlo);
    cudaGetSymbolAddress((void**)&hhi, g_hhi);   cudaGetSymbolAddress((void**)&hlo, g_hlo);
    cudaGetSymbolAddress((void**)&z1hi, g_z1hi); cudaGetSymbolAddress((void**)&z1lo, g_z1lo);
    cudaGetSymbolAddress((void**)&rhi, g_rhi);   cudaGetSymbolAddress((void**)&rlo, g_rlo);
    cudaGetSymbolAddress((void**)&rhhi, g_rhhi); cudaGetSymbolAddress((void**)&rhlo, g_rhlo);
    cudaGetSymbolAddress((void**)&hthi, g_hthi); cudaGetSymbolAddress((void**)&htlo, g_htlo);
    cudaGetSymbolAddress((void**)&omzhi, g_omzhi); cudaGetSymbolAddress((void**)&omzlo, g_omzlo);
    cudaGetSymbolAddress((void**)&zhthi, g_zhthi); cudaGetSymbolAddress((void**)&zhtlo, g_zhtlo);
    cudaGetSymbolAddress((void**)&z2hhi, g_z2hhi); cudaGetSymbolAddress((void**)&z2hlo, g_z2hlo);
    cudaGetSymbolAddress((void**)&WLhi, g_WLhi); cudaGetSymbolAddress((void**)&WLlo, g_WLlo);
    cudaGetSymbolAddress((void**)&WRhi, g_WRhi); cudaGetSymbolAddress((void**)&WRlo, g_WRlo);

    cudaFuncSetAttribute(mma_gemm<2,1>, cudaFuncAttributeMaxDynamicSharedMemorySize, SMEM_TOT);
    cudaFuncSetAttribute(mma_gemm<2,0>, cudaFuncAttributeMaxDynamicSharedMemorySize, SMEM_TOT);
    cudaFuncSetAttribute(mma_gemm<1,2>, cudaFuncAttributeMaxDynamicSharedMemorySize, SMEM_TOT);
    cudaFuncSetAttribute(mma_gemm<1,3>, cudaFuncAttributeMaxDynamicSharedMemorySize, SMEM_TOT);

    dim3 blk(256);
    dim3 gSig(2, BATCH / 128);    // N=256
    dim3 gCand(6, BATCH / 128);   // N=768
    int mixGrid = BATCH / 8;

    init_kernel<<<1, 32>>>();
    prep_w<<<768, 256>>>(L, WLhi, WLlo);
    prep_w<<<768, 256>>>(R, WRhi, WRlo);
    prep_a<<<BATCH * HID / 256, 256>>>(x, xhi, xlo);
    prep_a<<<BATCH * HID / 256, 256>>>(h, hhi, hlo);

    // z1 = z2 = sigmoid(x@L0 + h@R0 + b0) -> scratch + G_node slots 0,2 + hi/lo
    mma_gemm<2,1><<<gSig, blk, SMEM_TOT>>>(xhi, xlo, WLhi, WLlo, hhi, hlo, WRhi, WRlo,
        b, z1p, HID, gnode + 0 * HID, GN_LD, gnode + 2 * HID, GN_LD, z1hi, z1lo);
    // r = sigmoid(x@L1 + h@R1 + b1)
    mma_gemm<2,1><<<gSig, blk, SMEM_TOT>>>(xhi, xlo, WLhi + 65536, WLlo + 65536,
        hhi, hlo, WRhi + 65536, WRlo + 65536,
        b + 256, rp, HID, gnode + 1 * HID, GN_LD, nullptr, 0, rhi, rlo);

    // rh = mixture(h@L + r@R + b)
    mma_gemm<2,0><<<gCand, blk, SMEM_TOT>>>(hhi, hlo, WLhi, WLlo, rhi, rlo, WRhi, WRlo,
        b, candp, 768, nullptr, 0, nullptr, 0, nullptr, nullptr);
    mixture_kernel<<<mixGrid, 256>>>(h, rp, Ws, b,
        rhp, HID, gnode + 3 * HID, GN_LD, rhhi, rhlo, 0, 0);
    // h_tilde = mixture(x@L + rh@R + b)
    mma_gemm<2,0><<<gCand, blk, SMEM_TOT>>>(xhi, xlo, WLhi, WLlo, rhhi, rhlo, WRhi, WRlo,
        b, candp, 768, nullptr, 0, nullptr, 0, nullptr, nullptr);
    mixture_kernel<<<mixGrid, 256>>>(x, rhp, Ws, b,
        htp, HID, gnode + 4 * HID, GN_LD, hthi, htlo, 0, 1);
    // oneMinusZ1 = mixture(1 - (z1@R + b))
    mma_gemm<1,2><<<gCand, blk, SMEM_TOT>>>(z1hi, z1lo, WRhi, WRlo,
        nullptr, nullptr, nullptr, nullptr,
        b, candp, 768, nullptr, 0, nullptr, 0, nullptr, nullptr);
    mixture_kernel<<<mixGrid, 256>>>(z1p, nullptr, Ws, b,
        omzp, HID, gnode + 5 * HID, GN_LD, omzhi, omzlo, 2, 2);
    // zh_tilde = mixture((ht@L)*(omz@R) + b): raw GEMMs, combine in mixture
    mma_gemm<1,3><<<gCand, blk, SMEM_TOT>>>(hthi, htlo, WLhi, WLlo,
        nullptr, nullptr, nullptr, nullptr,
        b, candp, 768, nullptr, 0, nullptr, 0, nullptr, nullptr);
    mma_gemm<1,3><<<gCand, blk, SMEM_TOT>>>(omzhi, omzlo, WRhi, WRlo,
        nullptr, nullptr, nullptr, nullptr,
        b, cand2p, 768, nullptr, 0, nullptr, 0, nullptr, nullptr);
    mixture_kernel<<<mixGrid, 256>>>(htp, omzp, Ws, b,
        zhtp, HID, gnode + 6 * HID, GN_LD, zhthi, zhtlo, 1, 3);
    // z2h = mixture((h@L)*(z1@R) + b)
    mma_gemm<1,3><<<gCand, blk, SMEM_TOT>>>(hhi, hlo, WLhi, WLlo,
        nullptr, nullptr, nullptr, nullptr,
        b, candp, 768, nullptr, 0, nullptr, 0, nullptr, nullptr);
    mma_gemm<1,3><<<gCand, blk, SMEM_TOT>>>(z1hi, z1lo, WRhi, WRlo,
        nullptr, nullptr, nullptr, nullptr,
        b, cand2p, 768, nullptr, 0, nullptr, 0, nullptr, nullptr);
    mixture_kernel<<<mixGrid, 256>>>(h, z1p, Ws, b,
        z2hp, HID, gnode + 7 * HID, GN_LD, z2hhi, z2hlo, 1, 4);
    // h_next = mixture(zht@L + z2h@R + b)
    mma_gemm<2,0><<<gCand, blk, SMEM_TOT>>>(zhthi, zhtlo, WLhi, WLlo, z2hhi, z2hlo, WRhi, WRlo,
        b, candp, 768, nullptr, 0, nullptr, 0, nullptr, nullptr);
    mixture_kernel<<<mixGrid, 256>>>(zhtp, z2hp, Ws, b,
        out, HID, gnode + 8 * HID, GN_LD, nullptr, nullptr, 0, 5);

    finalize_kernel<<<1, 32>>>(out);
}

// round 8
// speedup vs baseline: 1.6649x; 1.0361x over previous
#include <cuda_runtime.h>
#include <cuda_bf16.h>
#include <math.h>
#include <stdint.h>

#define BATCH 16384
#define HID 256

// Output layout (float32):
//   [0, 4194304)            h_next  (B,1,256)
//   [4194304, 4194313)      G_structure (9 floats)
//   [4194313, 41943049)     G_node  (B,9,256)   <-- base NOT 16B-aligned (offset 9 floats)
//   [41943049, 41943055)    margins (6)
#define OFF_GS 4194304ul
#define OFF_GN 4194313ul
#define OFF_MG 41943049ul
#define GN_LD  2304

// ---------------------------------------------------------------------------
// Scratch (device globals). 16B-aligned (vector access).
// ---------------------------------------------------------------------------
__device__ __align__(16) float g_cand [(size_t)BATCH * 768];
__device__ __align__(16) float g_cand2[(size_t)BATCH * 768];
__device__ __align__(16) float g_cand3[(size_t)BATCH * 768];
__device__ __align__(16) float g_cand4[(size_t)BATCH * 768];
__device__ __align__(16) float g_z1 [(size_t)BATCH * HID];
__device__ __align__(16) float g_r  [(size_t)BATCH * HID];
__device__ __align__(16) float g_rh [(size_t)BATCH * HID];
__device__ __align__(16) float g_ht [(size_t)BATCH * HID];
__device__ __align__(16) float g_omz[(size_t)BATCH * HID];
__device__ __align__(16) float g_zht[(size_t)BATCH * HID];
__device__ __align__(16) float g_z2h[(size_t)BATCH * HID];
__device__ double g_ssum[24];

// split-bf16 activations (hi/lo)
#define ACT_ELEMS ((size_t)BATCH * HID)
__device__ __align__(16) __nv_bfloat16 g_xhi[ACT_ELEMS],  g_xlo[ACT_ELEMS];
__device__ __align__(16) __nv_bfloat16 g_hhi[ACT_ELEMS],  g_hlo[ACT_ELEMS];
__device__ __align__(16) __nv_bfloat16 g_z1hi[ACT_ELEMS], g_z1lo[ACT_ELEMS];
__device__ __align__(16) __nv_bfloat16 g_rhi[ACT_ELEMS],  g_rlo[ACT_ELEMS];
__device__ __align__(16) __nv_bfloat16 g_rhhi[ACT_ELEMS], g_rhlo[ACT_ELEMS];
__device__ __align__(16) __nv_bfloat16 g_hthi[ACT_ELEMS], g_htlo[ACT_ELEMS];
__device__ __align__(16) __nv_bfloat16 g_omzhi[ACT_ELEMS],g_omzlo[ACT_ELEMS];
__device__ __align__(16) __nv_bfloat16 g_zhthi[ACT_ELEMS],g_zhtlo[ACT_ELEMS];
__device__ __align__(16) __nv_bfloat16 g_z2hhi[ACT_ELEMS],g_z2hlo[ACT_ELEMS];

// split-bf16 weights, transposed [slab][n][k], slabs 0..2
#define W_ELEMS (3 * 65536)
__device__ __align__(16) __nv_bfloat16 g_WLhi[W_ELEMS], g_WLlo[W_ELEMS];
__device__ __align__(16) __nv_bfloat16 g_WRhi[W_ELEMS], g_WRlo[W_ELEMS];

__global__ void init_kernel() {
    int t = threadIdx.x;
    if (t < 24) g_ssum[t] = 0.0;
}

// W[s][k][n] fp32 -> hi/lo[s][n][k] bf16 (slabs 0..2); z: 0=L, 1=R
__global__ void prep_w(const float* __restrict__ WL, const float* __restrict__ WR,
                       __nv_bfloat16* __restrict__ hiL, __nv_bfloat16* __restrict__ loL,
                       __nv_bfloat16* __restrict__ hiR, __nv_bfloat16* __restrict__ loR) {
    const float* W = blockIdx.z ? WR : WL;
    __nv_bfloat16* hi = blockIdx.z ? hiR : hiL;
    __nv_bfloat16* lo = blockIdx.z ? loR : loL;
    int i = blockIdx.x * 256 + threadIdx.x;          // s*65536 + k*256 + n
    int s = i >> 16, rem = i & 65535, k = rem >> 8, n = rem & 255;
    float v = W[i];
    __nv_bfloat16 h = __float2bfloat16(v);
    size_t o = (size_t)s * 65536 + (size_t)n * 256 + k;
    hi[o] = h;
    lo[o] = __float2bfloat16(v - __bfloat162float(h));
}

// z: 0=x, 1=h
__global__ void prep_a(const float* __restrict__ X, const float* __restrict__ H,
                       __nv_bfloat16* __restrict__ xhi, __nv_bfloat16* __restrict__ xlo,
                       __nv_bfloat16* __restrict__ hhi, __nv_bfloat16* __restrict__ hlo) {
    const float* A = blockIdx.z ? H : X;
    __nv_bfloat16* hi = blockIdx.z ? hhi : xhi;
    __nv_bfloat16* lo = blockIdx.z ? hlo : xlo;
    size_t i = (size_t)blockIdx.x * 256 + threadIdx.x;
    float v = A[i];
    __nv_bfloat16 h = __float2bfloat16(v);
    hi[i] = h;
    lo[i] = __float2bfloat16(v - __bfloat162float(h));
}

// ---------------------------------------------------------------------------
// Tensor-core GEMM via warp mma.sync (bf16, fp32 accum), 3-term split:
//   A@W = Ahi@Whi + Alo@Whi + Ahi@Wlo  (virtual K = 768/pair; NPAIR 2 -> 1536)
// EPI 0:+bias  1:sigmoid(+bias)  2:1-(v+bias)  3:raw
// CTA 128x128, 8 warps (2x4), warp tile 64x32, cp.async 2-stage,
// ONE syncthreads per chunk, A-fragment register double-buffer.
// blockIdx.z selects one of up to 4 argument sets (merged launches).
// ---------------------------------------------------------------------------
#define SROW 144                      // padded smem row bytes (64 bf16 + 8 pad)
#define SAB  18432                    // one tile (128 * 144)
#define SMEM_TOT (4 * SAB)            // 2 stages x (A|B)

struct GArgs {
    const __nv_bfloat16 *A1hi, *A1lo, *B1hi, *B1lo;
    const __nv_bfloat16 *A2hi, *A2lo, *B2hi, *B2lo;
    const float* bias;
    float* C;  int ldc;
    float* C2; int ldc2;
    float* C3; int ldc3;
    __nv_bfloat16 *Ohi, *Olo;
};

__device__ __forceinline__ uint32_t smem_u32(const void* p) {
    uint32_t a;
    asm("{ .reg .u64 t; cvta.to.shared.u64 t, %1; cvt.u32.u64 %0, t; }" : "=r"(a) : "l"(p));
    return a;
}
#define CP_ASYNC16(dst, src) \
    asm volatile("cp.async.cg.shared.global [%0], [%1], 16;" :: "r"(dst), "l"(src))
#define CP_COMMIT() asm volatile("cp.async.commit_group;")
#define LDSM_X4(r, addr) \
    asm volatile("ldmatrix.sync.aligned.m8n8.x4.shared.b16 {%0,%1,%2,%3}, [%4];" \
        : "=r"((r)[0]), "=r"((r)[1]), "=r"((r)[2]), "=r"((r)[3]) : "r"(addr))
#define MMA16816(c, a, b0, b1) \
    asm volatile("mma.sync.aligned.m16n8k16.row.col.f32.bf16.bf16.f32 " \
        "{%0,%1,%2,%3}, {%4,%5,%6,%7}, {%8,%9}, {%0,%1,%2,%3};" \
        : "+f"((c)[0]), "+f"((c)[1]), "+f"((c)[2]), "+f"((c)[3]) \
        : "r"((a)[0]), "r"((a)[1]), "r"((a)[2]), "r"((a)[3]), "r"(b0), "r"(b1))

template<int NPAIR, int EPI>
__global__ void __launch_bounds__(256, 2) mma_gemm(GArgs g0, GArgs g1, GArgs g2, GArgs g3)
{
    const GArgs& G = (blockIdx.z == 0) ? g0 : (blockIdx.z == 1) ? g1
                   : (blockIdx.z == 2) ? g2 : g3;
    extern __shared__ __align__(16) char smem[];
    const int tid = threadIdx.x, wid = tid >> 5, lane = tid & 31;
    const int wm = wid >> 2, wn = wid & 3;
    const int bm0 = blockIdx.y * 128;
    const int nglob = blockIdx.x * 128;
    const int slab = nglob >> 8, nr = nglob & 255;
    const uint32_t sb = smem_u32(smem);
    constexpr int NCH = NPAIR * 12;

    const int lr = tid >> 1, lh = tid & 1;
    const size_t gArow = (size_t)(bm0 + lr) * 256 + lh * 32;
    const size_t gBrow = (size_t)slab * 65536 + (size_t)(nr + lr) * 256 + lh * 32;
    const uint32_t sOff = lr * SROW + lh * 64;

    auto issue = [&](int c) {
        const int p  = (NPAIR == 2) ? (c / 12) : 0;
        const int cc = (NPAIR == 2) ? (c % 12) : c;
        const int seg = cc >> 2;
        const int k0 = (cc & 3) * 64;
        const __nv_bfloat16* gA = (seg == 1) ? (p ? G.A2lo : G.A1lo) : (p ? G.A2hi : G.A1hi);
        const __nv_bfloat16* gB = (seg == 2) ? (p ? G.B2lo : G.B1lo) : (p ? G.B2hi : G.B1hi);
        const char* srcA = (const char*)(gA + gArow + k0);
        const char* srcB = (const char*)(gB + gBrow + k0);
        const int buf = c & 1;
        uint32_t dA = sb + buf * 2 * SAB + sOff;
        uint32_t dB = sb + buf * 2 * SAB + SAB + sOff;
        #pragma unroll
        for (int i = 0; i < 4; i++) CP_ASYNC16(dA + i * 16, srcA + i * 16);
        #pragma unroll
        for (int i = 0; i < 4; i++) CP_ASYNC16(dB + i * 16, srcB + i * 16);
    };

    float acc[4][4][4];
    #pragma unroll
    for (int i = 0; i < 4; i++)
        #pragma unroll
        for (int j = 0; j < 4; j++)
            #pragma unroll
            for (int t = 0; t < 4; t++) acc[i][j][t] = 0.f;

    const uint32_t aLane = (lane & 15) * SROW + (lane >> 4) * 16;
    const uint32_t bLane = ((lane & 7) + ((lane >= 16) ? 8 : 0)) * SROW + ((lane >> 3) & 1) * 16;

    issue(0); CP_COMMIT();

    #pragma unroll 1
    for (int c = 0; c < NCH; c++) {
        asm volatile("cp.async.wait_group 0;");
        __syncthreads();
        if (c + 1 < NCH) { issue(c + 1); CP_COMMIT(); }

        const int buf = c & 1;
        const uint32_t aBase = sb + buf * 2 * SAB + (wm * 64) * SROW + aLane;
        const uint32_t bBase = sb + buf * 2 * SAB + SAB + (wn * 32) * SROW + bLane;

        uint32_t a[2][4][4];
        #pragma unroll
        for (int mt = 0; mt < 4; mt++)
            LDSM_X4(a[0][mt], aBase + mt * 16 * SROW);

        #pragma unroll
        for (int ks = 0; ks < 4; ks++) {
            uint32_t bf[2][4];
            #pragma unroll
            for (int np = 0; np < 2; np++)
                LDSM_X4(bf[np], bBase + np * 16 * SROW + ks * 32);
            if (ks < 3) {
                #pragma unroll
                for (int mt = 0; mt < 4; mt++)
                    LDSM_X4(a[(ks + 1) & 1][mt], aBase + mt * 16 * SROW + (ks + 1) * 32);
            }
            #pragma unroll
            for (int mt = 0; mt < 4; mt++)
                #pragma unroll
                for (int nt = 0; nt < 4; nt++)
                    MMA16816(acc[mt][nt], a[ks & 1][mt],
                             bf[nt >> 1][(nt & 1) * 2], bf[nt >> 1][(nt & 1) * 2 + 1]);
        }
    }

    // Epilogue
    const int lr4 = lane >> 2, lc2 = (lane & 3) * 2;
    #pragma unroll
    for (int mt = 0; mt < 4; mt++) {
        #pragma unroll
        for (int nt = 0; nt < 4; nt++) {
            const int row0 = bm0 + wm * 64 + mt * 16 + lr4;
            const int gcol = nglob + wn * 32 + nt * 8 + lc2;
            const float b0v = (EPI != 3) ? G.bias[gcol] : 0.f;
            const float b1v = (EPI != 3) ? G.bias[gcol + 1] : 0.f;
            #pragma unroll
            for (int half = 0; half < 2; half++) {
                const int row = row0 + half * 8;
                float t0 = acc[mt][nt][half * 2 + 0] + b0v;
                float t1 = acc[mt][nt][half * 2 + 1] + b1v;
                if (EPI == 1) { t0 = 1.f / (1.f + expf(-t0)); t1 = 1.f / (1.f + expf(-t1)); }
                if (EPI == 2) { t0 = 1.f - t0; t1 = 1.f - t1; }
                float2 v = make_float2(t0, t1);
                *(float2*)(G.C + (size_t)row * G.ldc + gcol) = v;
                if (G.C2) {                      // G_node mirror: misaligned base
                    float* p2 = G.C2 + (size_t)row * G.ldc2 + gcol;
                    p2[0] = t0; p2[1] = t1;
                }
                if (G.C3) {
                    float* p3 = G.C3 + (size_t)row * G.ldc3 + gcol;
                    p3[0] = t0; p3[1] = t1;
                }
                if (G.Ohi) {
                    __nv_bfloat16 h0 = __float2bfloat16(t0);
                    __nv_bfloat16 h1 = __float2bfloat16(t1);
                    __nv_bfloat162 hv; hv.x = h0; hv.y = h1;
                    __nv_bfloat162 lv;
                    lv.x = __float2bfloat16(t0 - __bfloat162float(h0));
                    lv.y = __float2bfloat16(t1 - __bfloat162float(h1));
                    *(__nv_bfloat162*)(G.Ohi + (size_t)row * HID + gcol) = hv;
                    *(__nv_bfloat162*)(G.Olo + (size_t)row * HID + gcol) = lv;
                }
            }
        }
    }
}

// ---------------------------------------------------------------------------
// Mixture. mode 0: k3 = a1+a2+b3 | mode 1: cands raw products (cand*cand2+b),
// k3 = a1*a2+b3 | mode 2: k3 = 1-(a1+b3). blockIdx.z selects arg set.
// ---------------------------------------------------------------------------
struct MArgs {
    const float *A1, *A2, *cand, *cand2, *ball;
    float* out1; int ld1;
    float* out2; int ld2;
    __nv_bfloat16 *Ohi, *Olo;
    int mode, stage;
};

__global__ void __launch_bounds__(256) mixture_kernel(MArgs m0, MArgs m1)
{
    const MArgs& M = blockIdx.z ? m1 : m0;
    __shared__ float sWs[256];
    __shared__ float sSc[8][4];
    extern __shared__ float dummy[];   // unused
    int tid = threadIdx.x;
    sWs[tid] = ((const float*)M.ball)[-0];  // placeholder avoided below
    __syncthreads();
    // NOTE: sWs actually filled from Ws pointer passed via out-of-band: see launch
    // (we refill properly here)
    // -- real fill:
    // (Ws pointer carried in M.cand2 for mode 2? no) -- see wsv below.
}

// The above placeholder approach is fragile; use a dedicated kernel signature.
__global__ void __launch_bounds__(256) mixture2_kernel(
    const float* __restrict__ Wsv, MArgs m0, MArgs m1)
{
    const MArgs& M = blockIdx.z ? m1 : m0;
    __shared__ float sWs[256];
    __shared__ float sSc[8][4];
    int tid = threadIdx.x;
    sWs[tid] = Wsv[tid];
    __syncthreads();

    int warp = tid >> 5, lane = tid & 31;
    size_t b = (size_t)blockIdx.x * 8 + warp;
    const float* crow  = M.cand  + b * 768;
    const float* crow2 = (M.mode == 1) ? (M.cand2 + b * 768) : nullptr;
    const float* bias3 = M.ball + 768;

    float c[4][8];
    #pragma unroll
    for (int k = 0; k < 3; k++)
        #pragma unroll
        for (int j = 0; j < 8; j++) {
            int d = j * 32 + lane;
            float v = crow[k * 256 + d];
            if (M.mode == 1) v = v * crow2[k * 256 + d] + M.ball[k * 256 + d];
            c[k][j] = v;
        }

    #pragma unroll
    for (int j = 0; j < 8; j++) {
        int d = j * 32 + lane;
        float a1 = M.A1[b * HID + d];
        float v;
        if (M.mode == 0)      v = a1 + M.A2[b * HID + d] + bias3[d];
        else if (M.mode == 1) v = a1 * M.A2[b * HID + d] + bias3[d];
        else                  v = 1.f - (a1 + bias3[d]);
        c[3][j] = v;
    }

    float sc[4];
    #pragma unroll
    for (int k = 0; k < 4; k++) {
        float p = 0.f;
        #pragma unroll
        for (int j = 0; j < 8; j++) p += c[k][j] * sWs[j * 32 + lane];
        #pragma unroll
        for (int o = 16; o > 0; o >>= 1) p += __shfl_xor_sync(0xffffffffu, p, o);
        sc[k] = p;
    }

    float mx = fmaxf(fmaxf(sc[0], sc[1]), fmaxf(sc[2], sc[3]));
    float e0 = expf(sc[0] - mx), e1 = expf(sc[1] - mx);
    float e2 = expf(sc[2] - mx), e3 = expf(sc[3] - mx);
    float inv = 1.f / (e0 + e1 + e2 + e3);

    #pragma unroll
    for (int j = 0; j < 8; j++) {
        int d = j * 32 + lane;
        float o = (e0 * c[0][j] + e1 * c[1][j] + e2 * c[2][j] + e3 * c[3][j]) * inv;
        M.out1[b * M.ld1 + d] = o;
        if (M.out2) M.out2[b * M.ld2 + d] = o;
        if (M.Ohi) {
            __nv_bfloat16 hv = __float2bfloat16(o);
            M.Ohi[b * HID + d] = hv;
            M.Olo[b * HID + d] = __float2bfloat16(o - __bfloat162float(hv));
        }
    }

    if (lane == 0) {
        sSc[warp][0] = sc[0]; sSc[warp][1] = sc[1];
        sSc[warp][2] = sc[2]; sSc[warp][3] = sc[3];
    }
    __syncthreads();
    if (tid < 4) {
        float s = 0.f;
        #pragma unroll
        for (int w = 0; w < 8; w++) s += sSc[w][tid];
        atomicAdd(&g_ssum[M.stage * 4 + tid], (double)s);
    }
}

__global__ void finalize_kernel(float* __restrict__ out) {
    if (threadIdx.x == 0 && blockIdx.x == 0) {
        float* gs = out + OFF_GS;
        float* mg = out + OFF_MG;
        gs[0] = 0.f; gs[1] = 1.f; gs[2] = 0.f;
        for (int s = 0; s < 6; s++) {
            double v[4];
            for (int k = 0; k < 4; k++) v[k] = g_ssum[s * 4 + k];
            int idx = 0; double m1 = v[0];
            for (int k = 1; k < 4; k++) if (v[k] > m1) { m1 = v[k]; idx = k; }
            double m2 = -1e300;
            for (int k = 0; k < 4; k++) if (k != idx && v[k] > m2) m2 = v[k];
            gs[3 + s] = (float)idx;
            mg[s] = (float)(m1 - m2);
        }
    }
}

// ---------------------------------------------------------------------------
extern "C" void kernel_launch(void* const* d_in, const int* in_sizes, int n_in,
                              void* d_out, int out_size) {
    const float* x  = (const float*)d_in[0];
    const float* h  = (const float*)d_in[1];
    const float* L  = (const float*)d_in[2];
    const float* R  = (const float*)d_in[3];
    const float* b  = (const float*)d_in[4];
    const float* Ws = (const float*)d_in[5];
    float* out = (float*)d_out;
    float* gnode = out + OFF_GN;

    float *z1p, *rp, *rhp, *htp, *omzp, *zhtp, *z2hp, *c1p, *c2p, *c3p, *c4p;
    cudaGetSymbolAddress((void**)&z1p,  g_z1);
    cudaGetSymbolAddress((void**)&rp,   g_r);
    cudaGetSymbolAddress((void**)&rhp,  g_rh);
    cudaGetSymbolAddress((void**)&htp,  g_ht);
    cudaGetSymbolAddress((void**)&omzp, g_omz);
    cudaGetSymbolAddress((void**)&zhtp, g_zht);
    cudaGetSymbolAddress((void**)&z2hp, g_z2h);
    cudaGetSymbolAddress((void**)&c1p, g_cand);
    cudaGetSymbolAddress((void**)&c2p, g_cand2);
    cudaGetSymbolAddress((void**)&c3p, g_cand3);
    cudaGetSymbolAddress((void**)&c4p, g_cand4);

    __nv_bfloat16 *xhi,*xlo,*hhi,*hlo,*z1hi,*z1lo,*rhi,*rlo,*rhhi,*rhlo,
                  *hthi,*htlo,*omzhi,*omzlo,*zhthi,*zhtlo,*z2hhi,*z2hlo,
                  *WLhi,*WLlo,*WRhi,*WRlo;
    cudaGetSymbolAddress((void**)&xhi, g_xhi);   cudaGetSymbolAddress((void**)&xlo, g_xlo);
    cudaGetSymbolAddress((void**)&hhi, g_hhi);   cudaGetSymbolAddress((void**)&hlo, g_hlo);
    cudaGetSymbolAddress((void**)&z1hi, g_z1hi); cudaGetSymbolAddress((void**)&z1lo, g_z1lo);
    cudaGetSymbolAddress((void**)&rhi, g_rhi);   cudaGetSymbolAddress((void**)&rlo, g_rlo);
    cudaGetSymbolAddress((void**)&rhhi, g_rhhi); cudaGetSymbolAddress((void**)&rhlo, g_rhlo);
    cudaGetSymbolAddress((void**)&hthi, g_hthi); cudaGetSymbolAddress((void**)&htlo, g_htlo);
    cudaGetSymbolAddress((void**)&omzhi, g_omzhi); cudaGetSymbolAddress((void**)&omzlo, g_omzlo);
    cudaGetSymbolAddress((void**)&zhthi, g_zhthi); cudaGetSymbolAddress((void**)&zhtlo, g_zhtlo);
    cudaGetSymbolAddress((void**)&z2hhi, g_z2hhi); cudaGetSymbolAddress((void**)&z2hlo, g_z2hlo);
    cudaGetSymbolAddress((void**)&WLhi, g_WLhi); cudaGetSymbolAddress((void**)&WLlo, g_WLlo);
    cudaGetSymbolAddress((void**)&WRhi, g_WRhi); cudaGetSymbolAddress((void**)&WRlo, g_WRlo);

    cudaFuncSetAttribute(mma_gemm<2,1>, cudaFuncAttributeMaxDynamicSharedMemorySize, SMEM_TOT);
    cudaFuncSetAttribute(mma_gemm<2,0>, cudaFuncAttributeMaxDynamicSharedMemorySize, SMEM_TOT);
    cudaFuncSetAttribute(mma_gemm<1,2>, cudaFuncAttributeMaxDynamicSharedMemorySize, SMEM_TOT);
    cudaFuncSetAttribute(mma_gemm<1,3>, cudaFuncAttributeMaxDynamicSharedMemorySize, SMEM_TOT);

    dim3 blk(256);
    int mixGrid = BATCH / 8;

    GArgs Z{};  // zeroed defaults

    init_kernel<<<1, 32>>>();
    prep_w<<<dim3(768, 1, 2), 256>>>(L, R, WLhi, WLlo, WRhi, WRlo);
    prep_a<<<dim3(BATCH * HID / 256, 1, 2), 256>>>(x, h, xhi, xlo, hhi, hlo);

    // z1 & r in one launch (z=0: z1, z=1: r)
    {
        GArgs a0 = {xhi, xlo, WLhi, WLlo, hhi, hlo, WRhi, WRlo, b,
                    z1p, HID, gnode + 0 * HID, GN_LD, gnode + 2 * HID, GN_LD, z1hi, z1lo};
        GArgs a1 = {xhi, xlo, WLhi + 65536, WLlo + 65536, hhi, hlo, WRhi + 65536, WRlo + 65536,
                    b + 256, rp, HID, gnode + 1 * HID, GN_LD, nullptr, 0, rhi, rlo};
        mma_gemm<2,1><<<dim3(2, BATCH / 128, 2), blk, SMEM_TOT>>>(a0, a1, a0, a0);
    }

    // rh = mixture(h@L + r@R + b)
    {
        GArgs a0 = {hhi, hlo, WLhi, WLlo, rhi, rlo, WRhi, WRlo, b,
                    c1p, 768, nullptr, 0, nullptr, 0, nullptr, nullptr};
        mma_gemm<2,0><<<dim3(6, BATCH / 128, 1), blk, SMEM_TOT>>>(a0, a0, a0, a0);
        MArgs m0 = {h, rp, c1p, nullptr, b, rhp, HID, gnode + 3 * HID, GN_LD, rhhi, rhlo, 0, 0};
        mixture2_kernel<<<dim3(mixGrid, 1, 1), 256>>>(Ws, m0, m0);
    }
    // h_tilde = mixture(x@L + rh@R + b)
    {
        GArgs a0 = {xhi, xlo, WLhi, WLlo, rhhi, rhlo, WRhi, WRlo, b,
                    c1p, 768, nullptr, 0, nullptr, 0, nullptr, nullptr};
        mma_gemm<2,0><<<dim3(6, BATCH / 128, 1), blk, SMEM_TOT>>>(a0, a0, a0, a0);
        MArgs m0 = {x, rhp, c1p, nullptr, b, htp, HID, gnode + 4 * HID, GN_LD, hthi, htlo, 0, 1};
        mixture2_kernel<<<dim3(mixGrid, 1, 1), 256>>>(Ws, m0, m0);
    }
    // oneMinusZ1 = mixture(1 - (z1@R + b))
    {
        GArgs a0 = {z1hi, z1lo, WRhi, WRlo, nullptr, nullptr, nullptr, nullptr, b,
                    c1p, 768, nullptr, 0, nullptr, 0, nullptr, nullptr};
        mma_gemm<1,2><<<dim3(6, BATCH / 128, 1), blk, SMEM_TOT>>>(a0, a0, a0, a0);
        MArgs m0 = {z1p, nullptr, c1p, nullptr, b, omzp, HID, gnode + 5 * HID, GN_LD,
                    omzhi, omzlo, 2, 2};
        mixture2_kernel<<<dim3(mixGrid, 1, 1), 256>>>(Ws, m0, m0);
    }
    // 4 product GEMMs in ONE launch: z0 ht@L, z1 omz@R, z2 h@L, z3 z1@R (raw)
    {
        GArgs a0 = {hthi, htlo, WLhi, WLlo, nullptr, nullptr, nullptr, nullptr, b,
                    c1p, 768, nullptr, 0, nullptr, 0, nullptr, nullptr};
        GArgs a1 = {omzhi, omzlo, WRhi, WRlo, nullptr, nullptr, nullptr, nullptr, b,
                    c2p, 768, nullptr, 0, nullptr, 0, nullptr, nullptr};
        GArgs a2 = {hhi, hlo, WLhi, WLlo, nullptr, nullptr, nullptr, nullptr, b,
                    c3p, 768, nullptr, 0, nullptr, 0, nullptr, nullptr};
        GArgs a3 = {z1hi, z1lo, WRhi, WRlo, nullptr, nullptr, nullptr, nullptr, b,
                    c4p, 768, nullptr, 0, nullptr, 0, nullptr, nullptr};
        mma_gemm<1,3><<<dim3(6, BATCH / 128, 4), blk, SMEM_TOT>>>(a0, a1, a2, a3);
    }
    // zh_tilde & z2h mixtures in one launch
    {
        MArgs m0 = {htp, omzp, c1p, c2p, b, zhtp, HID, gnode + 6 * HID, GN_LD,
                    zhthi, zhtlo, 1, 3};
        MArgs m1 = {h, z1p, c3p, c4p, b, z2hp, HID, gnode + 7 * HID, GN_LD,
                    z2hhi, z2hlo, 1, 4};
        mixture2_kernel<<<dim3(mixGrid, 1, 2), 256>>>(Ws, m0, m1);
    }
    // h_next = mixture(zht@L + z2h@R + b)
    {
        GArgs a0 = {zhthi, zhtlo, WLhi, WLlo, z2hhi, z2hlo, WRhi, WRlo, b,
                    c1p, 768, nullptr, 0, nullptr, 0, nullptr, nullptr};
        mma_gemm<2,0><<<dim3(6, BATCH / 128, 1), blk, SMEM_TOT>>>(a0, a0, a0, a0);
        MArgs m0 = {zhtp, z2hp, c1p, nullptr, b, out, HID, gnode + 8 * HID, GN_LD,
                    nullptr, nullptr, 0, 5};
        mixture2_kernel<<<dim3(mixGrid, 1, 1), 256>>>(Ws, m0, m0);
    }

    finalize_kernel<<<1, 32>>>(out);
}